// round 2
// baseline (speedup 1.0000x reference)
#include <cuda_runtime.h>
#include <math.h>

// ---------------- problem constants ----------------
#define BB     2
#define S0C    1536
#define S1C    384
#define S2C    128
#define SS     2048
#define HIDC   896
#define NHC    14
#define NKVC   2
#define HDC    64
#define INTERC 4864
#define MROWS  (BB*SS)          // 4096 token rows

// ---------------- scratch (device global, allocation-free) ----------------
#define OFF_H   0ull
#define OFF_Q   3670016ull
#define OFF_K   7340032ull
#define OFF_V   7864320ull
#define OFF_ATT 8388608ull
#define OFF_O1  12058624ull
#define OFF_H2  15728640ull
#define OFF_G   19398656ull
#define SCRATCH_FLOATS 39321600ull

__device__ float g_buf[SCRATCH_FLOATS];

// ---------------- RMSNorm (warp per token) ----------------
// SRC=0: read from x0/x1/x2 segment inputs; SRC=1: read from contiguous buffer
template<int SRC>
__global__ __launch_bounds__(256) void rms_kernel(
    const float* __restrict__ x0, const float* __restrict__ x1,
    const float* __restrict__ x2, const float* __restrict__ inbuf,
    const float* __restrict__ w, float* __restrict__ out)
{
    int warp = (blockIdx.x * blockDim.x + threadIdx.x) >> 5;
    if (warp >= MROWS) return;
    int lane = threadIdx.x & 31;
    int b = warp >> 11, s = warp & 2047;
    const float* xp;
    int seg;
    if (SRC == 0) {
        if (s < S0C)            { seg = 0; xp = x0 + ((size_t)b*S0C + s)        * HIDC; }
        else if (s < S0C+S1C)   { seg = 1; xp = x1 + ((size_t)b*S1C + (s-S0C))  * HIDC; }
        else                    { seg = 2; xp = x2 + ((size_t)b*S2C + (s-S0C-S1C)) * HIDC; }
    } else {
        seg = (s < S0C) ? 0 : ((s < S0C+S1C) ? 1 : 2);
        xp = inbuf + (size_t)warp * HIDC;
    }
    float vals[28];
    float ss = 0.f;
#pragma unroll
    for (int i = 0; i < 28; i++) { float v = xp[lane + i*32]; vals[i] = v; ss += v*v; }
#pragma unroll
    for (int o = 16; o > 0; o >>= 1) ss += __shfl_xor_sync(0xffffffffu, ss, o);
    float rs = rsqrtf(ss * (1.0f/896.0f) + 1e-6f);
    const float* wp = w + seg * HIDC;
    float* op = out + (size_t)warp * HIDC;
#pragma unroll
    for (int i = 0; i < 28; i++) { int c = lane + i*32; op[c] = vals[i] * rs * wp[c]; }
}

// ---------------- SGEMM: C[M,N] = A[M,K] @ W[seg,N,K]^T (+ epilogue) ----------------
// BM=128, BN=64, BK=16, 256 threads, 8x4 per thread.
// MODE 0: += bias[seg,N]              (QKV projections)
// MODE 1: plain                       (gate proj)
// MODE 2: += x-segment residual       (o-proj)
// MODE 3: += res buffer               (down-proj -> d_out)
// MODE 4: C = silu(res) * acc         (up proj fused with SwiGLU, in-place on res)
template<int MODE>
__global__ __launch_bounds__(256) void gemm_kernel(
    const float* __restrict__ A, const float* __restrict__ W,
    const float* __restrict__ bias, const float* __restrict__ res,
    float* __restrict__ C, int N, int K,
    const float* __restrict__ x0, const float* __restrict__ x1,
    const float* __restrict__ x2)
{
    __shared__ float As[16*128];
    __shared__ float Bs[16*64];
    int tid = threadIdx.x;
    int mb = blockIdx.y * 128;
    int nb = blockIdx.x * 64;
    int srow = mb & 2047;
    int seg = (srow < S0C) ? 0 : ((srow < S0C+S1C) ? 1 : 2);
    const float* Wp = W + (size_t)seg * N * K;

    int am = tid >> 1, ak = (tid & 1) * 8;     // A: 128 rows x 16 k, 8 floats/thread
    int bn = tid >> 2, bk = (tid & 3) * 4;     // B: 64 rows x 16 k, 4 floats/thread
    const float* Aptr = A  + (size_t)(mb + am) * K + ak;
    const float* Bptr = Wp + (size_t)(nb + bn) * K + bk;

    int ty = tid >> 4, tx = tid & 15;
    float4 acc[8];
#pragma unroll
    for (int i = 0; i < 8; i++) acc[i] = make_float4(0.f,0.f,0.f,0.f);

    for (int kt = 0; kt < K; kt += 16) {
        float4 a0 = *(const float4*)(Aptr + kt);
        float4 a1 = *(const float4*)(Aptr + kt + 4);
        float4 b0 = *(const float4*)(Bptr + kt);
        __syncthreads();
        As[(ak+0)*128 + am] = a0.x; As[(ak+1)*128 + am] = a0.y;
        As[(ak+2)*128 + am] = a0.z; As[(ak+3)*128 + am] = a0.w;
        As[(ak+4)*128 + am] = a1.x; As[(ak+5)*128 + am] = a1.y;
        As[(ak+6)*128 + am] = a1.z; As[(ak+7)*128 + am] = a1.w;
        Bs[(bk+0)*64 + bn] = b0.x; Bs[(bk+1)*64 + bn] = b0.y;
        Bs[(bk+2)*64 + bn] = b0.z; Bs[(bk+3)*64 + bn] = b0.w;
        __syncthreads();
#pragma unroll
        for (int k = 0; k < 16; k++) {
            float4 bv = *(const float4*)&Bs[k*64 + tx*4];
            float4 m0 = *(const float4*)&As[k*128 + ty*8];
            float4 m1 = *(const float4*)&As[k*128 + ty*8 + 4];
            float amv[8] = {m0.x,m0.y,m0.z,m0.w,m1.x,m1.y,m1.z,m1.w};
#pragma unroll
            for (int i = 0; i < 8; i++) {
                acc[i].x = fmaf(amv[i], bv.x, acc[i].x);
                acc[i].y = fmaf(amv[i], bv.y, acc[i].y);
                acc[i].z = fmaf(amv[i], bv.z, acc[i].z);
                acc[i].w = fmaf(amv[i], bv.w, acc[i].w);
            }
        }
    }

    int row0 = mb + ty*8, col0 = nb + tx*4;

    // MODE 2: x-segment residual setup (segment constant per block)
    const float* xp = nullptr; int xstart = 0, xseq = 0;
    if (MODE == 2) {
        if (seg == 0)      { xp = x0; xstart = 0;        xseq = S0C; }
        else if (seg == 1) { xp = x1; xstart = S0C;      xseq = S1C; }
        else               { xp = x2; xstart = S0C+S1C;  xseq = S2C; }
    }

#pragma unroll
    for (int i = 0; i < 8; i++) {
        int row = row0 + i;
        float4 o = acc[i];
        if (MODE == 0) {
            float4 bv = *(const float4*)&bias[seg*N + col0];
            o.x += bv.x; o.y += bv.y; o.z += bv.z; o.w += bv.w;
        } else if (MODE == 2) {
            int b = row >> 11, s = row & 2047;
            float4 rv = *(const float4*)&xp[((size_t)b*xseq + (s - xstart))*HIDC + col0];
            o.x += rv.x; o.y += rv.y; o.z += rv.z; o.w += rv.w;
        } else if (MODE == 3) {
            float4 rv = *(const float4*)&res[(size_t)row*N + col0];
            o.x += rv.x; o.y += rv.y; o.z += rv.z; o.w += rv.w;
        } else if (MODE == 4) {
            float4 gv = *(const float4*)&res[(size_t)row*N + col0];
            o.x *= gv.x / (1.0f + __expf(-gv.x));
            o.y *= gv.y / (1.0f + __expf(-gv.y));
            o.z *= gv.z / (1.0f + __expf(-gv.z));
            o.w *= gv.w / (1.0f + __expf(-gv.w));
        }
        *(float4*)&C[(size_t)row*N + col0] = o;
    }
}

// ---------------- RoPE (in-place on q and k buffers) ----------------
__global__ __launch_bounds__(256) void rope_kernel(float* __restrict__ q,
                                                   float* __restrict__ k)
{
    int idx = blockIdx.x * blockDim.x + threadIdx.x;
    if (idx >= MROWS * 16 * 32) return;
    int i   = idx & 31;
    int hs  = (idx >> 5) & 15;
    int tok = idx >> 9;
    int pos = tok & 2047;                         // position_ids = arange(S)
    float invf = powf(1.0e6f, -(float)i * (1.0f/32.0f));
    float fr = (float)pos * invf;
    float sn, cs; sincosf(fr, &sn, &cs);
    float* base;
    if (hs < NHC) base = q + (size_t)tok*HIDC + hs*HDC;
    else          base = k + (size_t)tok*(NKVC*HDC) + (hs - NHC)*HDC;
    float v1 = base[i], v2 = base[i+32];
    base[i]    = v1*cs - v2*sn;
    base[i+32] = v2*cs + v1*sn;
}

// ---------------- Attention (flash, 64q x 64k tiles) ----------------
// mask: allowed(q,k) = (k < S0) || (k <= q)   (prefix-LM)
// thread (r = tid>>2, j = tid&3): score cols c = 4*i + j, output dims d = j*16..+15
__global__ __launch_bounds__(256) void attn_kernel(
    const float* __restrict__ q, const float* __restrict__ k,
    const float* __restrict__ v, float* __restrict__ o)
{
    extern __shared__ float sm[];
    float* qs = sm;                 // [64][68]
    float* ks = sm + 64*68;
    float* vs = sm + 2*64*68;
    int qb = blockIdx.x, h = blockIdx.y, b = blockIdx.z;
    int tid = threadIdx.x, lane = tid & 31;
    int r = tid >> 2, j = tid & 3, j16 = j << 4;
    int kvh = h / 7;

    const float* qbase = q + (size_t)(b*SS + qb*64) * HIDC + h*HDC;
    for (int idx = tid; idx < 4096; idx += 256) {
        int row = idx >> 6, d = idx & 63;
        qs[row*68 + d] = qbase[(size_t)row*HIDC + d] * 0.125f;  // 1/sqrt(64)
    }
    const float* kb0 = k + (size_t)b*SS*(NKVC*HDC) + kvh*HDC;
    const float* vb0 = v + (size_t)b*SS*(NKVC*HDC) + kvh*HDC;

    float4 acc4[4];
#pragma unroll
    for (int t = 0; t < 4; t++) acc4[t] = make_float4(0.f,0.f,0.f,0.f);
    float mrow = -INFINITY, lrow = 0.f;
    int sqr = qb*64 + r;
    int ntiles = (qb + 1 > 24) ? (qb + 1) : 24;   // 24 = S0/64 prefix tiles

    for (int t = 0; t < ntiles; t++) {
        __syncthreads();
        int kbase = t * 64;
        for (int idx = tid; idx < 4096; idx += 256) {
            int row = idx >> 6, d = idx & 63;
            ks[row*68 + d] = kb0[(size_t)(kbase+row)*(NKVC*HDC) + d];
            vs[row*68 + d] = vb0[(size_t)(kbase+row)*(NKVC*HDC) + d];
        }
        __syncthreads();

        // scores: e[i] = q_row . k_col,  col c = 4*i + j
        float e[16];
#pragma unroll
        for (int i = 0; i < 16; i++) e[i] = 0.f;
        const float* qrow = &qs[r*68];
#pragma unroll
        for (int dc = 0; dc < 4; dc++) {
            float4 q4[4];
#pragma unroll
            for (int tt = 0; tt < 4; tt++) q4[tt] = *(const float4*)(qrow + dc*16 + tt*4);
#pragma unroll
            for (int i = 0; i < 16; i++) {
                const float* kr = &ks[(4*i + j)*68 + dc*16];
#pragma unroll
                for (int tt = 0; tt < 4; tt++) {
                    float4 k4 = *(const float4*)(kr + tt*4);
                    e[i] = fmaf(q4[tt].x, k4.x,
                           fmaf(q4[tt].y, k4.y,
                           fmaf(q4[tt].z, k4.z,
                           fmaf(q4[tt].w, k4.w, e[i]))));
                }
            }
        }
        // mask + row max
        bool full = (kbase + 63 < S0C) || (kbase + 63 <= sqr);
        float tmax = -INFINITY;
        if (full) {
#pragma unroll
            for (int i = 0; i < 16; i++) tmax = fmaxf(tmax, e[i]);
        } else {
#pragma unroll
            for (int i = 0; i < 16; i++) {
                int kk = kbase + 4*i + j;
                if (!(kk < S0C || kk <= sqr)) e[i] = -INFINITY;
                tmax = fmaxf(tmax, e[i]);
            }
        }
        tmax = fmaxf(tmax, __shfl_xor_sync(0xffffffffu, tmax, 1));
        tmax = fmaxf(tmax, __shfl_xor_sync(0xffffffffu, tmax, 2));
        float mnew = fmaxf(mrow, tmax);
        float corr = __expf(mrow - mnew);
        lrow *= corr;
#pragma unroll
        for (int t4 = 0; t4 < 4; t4++) {
            acc4[t4].x *= corr; acc4[t4].y *= corr;
            acc4[t4].z *= corr; acc4[t4].w *= corr;
        }
        float rsum = 0.f;
#pragma unroll
        for (int i = 0; i < 16; i++) { e[i] = __expf(e[i] - mnew); rsum += e[i]; }
        rsum += __shfl_xor_sync(0xffffffffu, rsum, 1);
        rsum += __shfl_xor_sync(0xffffffffu, rsum, 2);
        lrow += rsum;
        mrow = mnew;

        // PV: O[r][d] += P[r][c] * V[c][d]; P broadcast via quarter-warp shuffle
#pragma unroll
        for (int c = 0; c < 64; c++) {
            float p = __shfl_sync(0xffffffffu, e[c >> 2], (lane & ~3) | (c & 3));
            const float* vr = &vs[c*68 + j16];
#pragma unroll
            for (int t4 = 0; t4 < 4; t4++) {
                float4 v4 = *(const float4*)(vr + t4*4);
                acc4[t4].x = fmaf(p, v4.x, acc4[t4].x);
                acc4[t4].y = fmaf(p, v4.y, acc4[t4].y);
                acc4[t4].z = fmaf(p, v4.z, acc4[t4].z);
                acc4[t4].w = fmaf(p, v4.w, acc4[t4].w);
            }
        }
    }

    float inv = 1.0f / lrow;
    float* op = o + (size_t)(b*SS + sqr) * HIDC + h*HDC + j16;
#pragma unroll
    for (int t4 = 0; t4 < 4; t4++) {
        float4 ov = acc4[t4];
        ov.x *= inv; ov.y *= inv; ov.z *= inv; ov.w *= inv;
        *(float4*)(op + t4*4) = ov;
    }
}

// ---------------- launcher ----------------
extern "C" void kernel_launch(void* const* d_in, const int* in_sizes, int n_in,
                              void* d_out, int out_size)
{
    const float* x0  = (const float*)d_in[0];
    const float* x1  = (const float*)d_in[1];
    const float* x2  = (const float*)d_in[2];
    const float* qW  = (const float*)d_in[3];
    const float* qb  = (const float*)d_in[4];
    const float* kW  = (const float*)d_in[5];
    const float* kb  = (const float*)d_in[6];
    const float* vW  = (const float*)d_in[7];
    const float* vb  = (const float*)d_in[8];
    const float* oW  = (const float*)d_in[9];
    const float* ln1 = (const float*)d_in[10];
    const float* ln2 = (const float*)d_in[11];
    const float* gW  = (const float*)d_in[12];
    const float* uW  = (const float*)d_in[13];
    const float* dW  = (const float*)d_in[14];
    float* out = (float*)d_out;

    float* sb = nullptr;
    cudaGetSymbolAddress((void**)&sb, g_buf);
    float* hb   = sb + OFF_H;
    float* qbuf = sb + OFF_Q;
    float* kbuf = sb + OFF_K;
    float* vbuf = sb + OFF_V;
    float* att  = sb + OFF_ATT;
    float* o1   = sb + OFF_O1;
    float* h2   = sb + OFF_H2;
    float* gb   = sb + OFF_G;

    // 1. pre-attention RMSNorm
    rms_kernel<0><<<512, 256>>>(x0, x1, x2, nullptr, ln1, hb);
    // 2. QKV projections (+bias)
    gemm_kernel<0><<<dim3(14, 32), 256>>>(hb, qW, qb, nullptr, qbuf, NHC*HDC,  HIDC, nullptr, nullptr, nullptr);
    gemm_kernel<0><<<dim3( 2, 32), 256>>>(hb, kW, kb, nullptr, kbuf, NKVC*HDC, HIDC, nullptr, nullptr, nullptr);
    gemm_kernel<0><<<dim3( 2, 32), 256>>>(hb, vW, vb, nullptr, vbuf, NKVC*HDC, HIDC, nullptr, nullptr, nullptr);
    // 3. RoPE
    rope_kernel<<<8192, 256>>>(qbuf, kbuf);
    // 4. attention
    cudaFuncSetAttribute(attn_kernel, cudaFuncAttributeMaxDynamicSharedMemorySize, 53248);
    attn_kernel<<<dim3(32, NHC, BB), 256, 3*64*68*4>>>(qbuf, kbuf, vbuf, att);
    // 5. o-proj + residual(x)
    gemm_kernel<2><<<dim3(14, 32), 256>>>(att, oW, nullptr, nullptr, o1, HIDC, HIDC, x0, x1, x2);
    // 6. post-attention RMSNorm
    rms_kernel<1><<<512, 256>>>(nullptr, nullptr, nullptr, o1, ln2, h2);
    // 7. gate proj
    gemm_kernel<1><<<dim3(76, 32), 256>>>(h2, gW, nullptr, nullptr, gb, INTERC, HIDC, nullptr, nullptr, nullptr);
    // 8. up proj fused with silu(g)*u (in-place on gb)
    gemm_kernel<4><<<dim3(76, 32), 256>>>(h2, uW, nullptr, gb, gb, INTERC, HIDC, nullptr, nullptr, nullptr);
    // 9. down-proj + residual(o1) -> output
    gemm_kernel<3><<<dim3(14, 32), 256>>>(gb, dW, nullptr, o1, out, HIDC, INTERC, nullptr, nullptr, nullptr);
}

// round 4
// speedup vs baseline: 1.6255x; 1.6255x over previous
#include <cuda_runtime.h>
#include <math.h>

// ---------------- problem constants ----------------
#define BB     2
#define S0C    1536
#define S1C    384
#define S2C    128
#define SS     2048
#define HIDC   896
#define NHC    14
#define NKVC   2
#define HDC    64
#define INTERC 4864
#define MROWS  (BB*SS)          // 4096 token rows

// ---------------- scratch (device global, allocation-free) ----------------
#define OFF_H   0ull
#define OFF_Q   3670016ull
#define OFF_K   7340032ull
#define OFF_V   7864320ull
#define OFF_ATT 8388608ull
#define OFF_O1  12058624ull
#define OFF_H2  15728640ull
#define OFF_G   19398656ull
#define SCRATCH_FLOATS 39321600ull

__device__ float g_buf[SCRATCH_FLOATS];

// ---------------- RMSNorm (warp per token) ----------------
template<int SRC>
__global__ __launch_bounds__(256) void rms_kernel(
    const float* __restrict__ x0, const float* __restrict__ x1,
    const float* __restrict__ x2, const float* __restrict__ inbuf,
    const float* __restrict__ w, float* __restrict__ out)
{
    int warp = (blockIdx.x * blockDim.x + threadIdx.x) >> 5;
    if (warp >= MROWS) return;
    int lane = threadIdx.x & 31;
    int b = warp >> 11, s = warp & 2047;
    const float* xp;
    int seg;
    if (SRC == 0) {
        if (s < S0C)            { seg = 0; xp = x0 + ((size_t)b*S0C + s)        * HIDC; }
        else if (s < S0C+S1C)   { seg = 1; xp = x1 + ((size_t)b*S1C + (s-S0C))  * HIDC; }
        else                    { seg = 2; xp = x2 + ((size_t)b*S2C + (s-S0C-S1C)) * HIDC; }
    } else {
        seg = (s < S0C) ? 0 : ((s < S0C+S1C) ? 1 : 2);
        xp = inbuf + (size_t)warp * HIDC;
    }
    float vals[28];
    float ss = 0.f;
#pragma unroll
    for (int i = 0; i < 28; i++) { float v = xp[lane + i*32]; vals[i] = v; ss += v*v; }
#pragma unroll
    for (int o = 16; o > 0; o >>= 1) ss += __shfl_xor_sync(0xffffffffu, ss, o);
    float rs = rsqrtf(ss * (1.0f/896.0f) + 1e-6f);
    const float* wp = w + seg * HIDC;
    float* op = out + (size_t)warp * HIDC;
#pragma unroll
    for (int i = 0; i < 28; i++) { int c = lane + i*32; op[c] = vals[i] * rs * wp[c]; }
}

// ---------------- TF32 tensor-core GEMM ----------------
// C[M,N] = A[M,K] @ W[seg,N,K]^T (+ epilogue)
// BM=128, BN=128, BK=16, 256 threads, warps 2(m) x 4(n), warp tile 64x32.
// MODE 1: plain (gate)     MODE 2: += x residual (o-proj)
// MODE 3: += res (down)    MODE 4: C = silu(res)*acc (up+SwiGLU)
// MODE 5: fused QKV (+bias), blockIdx.x: 0-6 q, 7 k, 8 v

struct GArgs {
    const float* A; const float* W; const float* bias; const float* res;
    float* C; int N; int K;
    const float* x0; const float* x1; const float* x2;
    const float* W2; const float* W3; const float* b2; const float* b3;
    float* C2; float* C3;
};

__device__ __forceinline__ unsigned f2t(float f) {
    unsigned u; asm("cvt.rna.tf32.f32 %0, %1;" : "=r"(u) : "f"(f)); return u;
}

__device__ __forceinline__ void mma8(float* c, const unsigned* a, const unsigned* b) {
    asm volatile(
        "mma.sync.aligned.m16n8k8.row.col.f32.tf32.tf32.f32 "
        "{%0,%1,%2,%3}, {%4,%5,%6,%7}, {%8,%9}, {%0,%1,%2,%3};"
        : "+f"(c[0]), "+f"(c[1]), "+f"(c[2]), "+f"(c[3])
        : "r"(a[0]), "r"(a[1]), "r"(a[2]), "r"(a[3]), "r"(b[0]), "r"(b[1]));
}

// store one float4 (k4*4..+3) of row m, with k-skew swizzle
__device__ __forceinline__ void stile(unsigned (*S)[136], int k4, int m, float4 v) {
    int mp = (m + 8*k4) & 127;
    S[k4*4+0][mp] = f2t(v.x);
    S[k4*4+1][mp] = f2t(v.y);
    S[k4*4+2][mp] = f2t(v.z);
    S[k4*4+3][mp] = f2t(v.w);
}

template<int MODE>
__global__ __launch_bounds__(256, 2) void gemm_tc(GArgs ga)
{
    __shared__ unsigned As[2][16][136];
    __shared__ unsigned Bs[2][16][136];
    int tid = threadIdx.x;
    int mb = blockIdx.y * 128;
    int srow = mb & 2047;
    int seg = (srow < S0C) ? 0 : ((srow < S0C+S1C) ? 1 : 2);

    const float* Wp; const float* bp = nullptr; float* Cp; int Nloc; int nb;
    if (MODE == 5) {
        int bx = blockIdx.x;
        if (bx < 7)       { Wp = ga.W;  bp = ga.bias; Cp = ga.C;  Nloc = 896; nb = bx*128; }
        else if (bx == 7) { Wp = ga.W2; bp = ga.b2;   Cp = ga.C2; Nloc = 128; nb = 0; }
        else              { Wp = ga.W3; bp = ga.b3;   Cp = ga.C3; Nloc = 128; nb = 0; }
        bp += seg * Nloc;
    } else {
        Wp = ga.W; Cp = ga.C; Nloc = ga.N; nb = blockIdx.x * 128;
    }
    int K = ga.K;
    Wp += (size_t)seg * Nloc * K;

    // global load mapping: thread -> (row pair, k-float4)
    int ldr  = tid >> 2;       // 0..63  (rows ldr and ldr+64)
    int ldk4 = tid & 3;        // which float4 of the 16-wide k slice
    const float* Ap = ga.A + (size_t)(mb + ldr) * K + ldk4*4;
    const float* Bp = Wp   + (size_t)(nb + ldr) * K + ldk4*4;
    size_t rowsk = (size_t)64 * K;

    int lane = tid & 31;
    int g = lane >> 2, tq = lane & 3;
    int w = tid >> 5;
    int warp_m = (w & 1) * 64, warp_n = (w >> 1) * 32;

    float acc[4][4][4];
#pragma unroll
    for (int i = 0; i < 4; i++)
#pragma unroll
        for (int jn = 0; jn < 4; jn++)
#pragma unroll
            for (int cc = 0; cc < 4; cc++) acc[i][jn][cc] = 0.f;

    int nsteps = K >> 4;

    // prologue: tile 0
    {
        float4 a0 = *(const float4*)Ap;
        float4 a1 = *(const float4*)(Ap + rowsk);
        float4 b0 = *(const float4*)Bp;
        float4 b1 = *(const float4*)(Bp + rowsk);
        stile(As[0], ldk4, ldr,     a0);
        stile(As[0], ldk4, ldr+64,  a1);
        stile(Bs[0], ldk4, ldr,     b0);
        stile(Bs[0], ldk4, ldr+64,  b1);
        Ap += 16; Bp += 16;
    }

    for (int s = 0; s < nsteps; s++) {
        __syncthreads();
        int cur = s & 1;
        float4 na0, na1, nb0, nb1;
        bool more = (s + 1 < nsteps);
        if (more) {
            na0 = *(const float4*)Ap;
            na1 = *(const float4*)(Ap + rowsk);
            nb0 = *(const float4*)Bp;
            nb1 = *(const float4*)(Bp + rowsk);
            Ap += 16; Bp += 16;
        }
#pragma unroll
        for (int ks = 0; ks < 2; ks++) {
            int kb = ks * 8;
            int off0 = (kb >> 2) * 8;       // 0 or 16
            int off1 = off0 + 8;
            unsigned af[4][4];
#pragma unroll
            for (int mt = 0; mt < 4; mt++) {
                int mA = warp_m + mt*16 + g;
                af[mt][0] = As[cur][kb+tq  ][(mA      + off0) & 127];
                af[mt][1] = As[cur][kb+tq  ][(mA + 8  + off0) & 127];
                af[mt][2] = As[cur][kb+tq+4][(mA      + off1) & 127];
                af[mt][3] = As[cur][kb+tq+4][(mA + 8  + off1) & 127];
            }
            unsigned bf[4][2];
#pragma unroll
            for (int nt = 0; nt < 4; nt++) {
                int nB = warp_n + nt*8 + g;
                bf[nt][0] = Bs[cur][kb+tq  ][(nB + off0) & 127];
                bf[nt][1] = Bs[cur][kb+tq+4][(nB + off1) & 127];
            }
#pragma unroll
            for (int mt = 0; mt < 4; mt++)
#pragma unroll
                for (int nt = 0; nt < 4; nt++)
                    mma8(acc[mt][nt], af[mt], bf[nt]);
        }
        if (more) {
            int nxt = cur ^ 1;
            stile(As[nxt], ldk4, ldr,    na0);
            stile(As[nxt], ldk4, ldr+64, na1);
            stile(Bs[nxt], ldk4, ldr,    nb0);
            stile(Bs[nxt], ldk4, ldr+64, nb1);
        }
    }

    // epilogue
    const float* xp = nullptr; int xstart = 0, xseq = 0;
    if (MODE == 2) {
        if (seg == 0)      { xp = ga.x0; xstart = 0;       xseq = S0C; }
        else if (seg == 1) { xp = ga.x1; xstart = S0C;     xseq = S1C; }
        else               { xp = ga.x2; xstart = S0C+S1C; xseq = S2C; }
    }

#pragma unroll
    for (int mt = 0; mt < 4; mt++) {
#pragma unroll
        for (int hh = 0; hh < 2; hh++) {
            int row = mb + warp_m + mt*16 + g + hh*8;
#pragma unroll
            for (int nt = 0; nt < 4; nt++) {
                int col = nb + warp_n + nt*8 + 2*tq;
                float o0 = acc[mt][nt][hh*2 + 0];
                float o1 = acc[mt][nt][hh*2 + 1];
                if (MODE == 5) {
                    o0 += bp[col]; o1 += bp[col+1];
                } else if (MODE == 2) {
                    int b = row >> 11, s = row & 2047;
                    const float* rr = xp + ((size_t)b*xseq + (s - xstart))*HIDC + col;
                    o0 += rr[0]; o1 += rr[1];
                } else if (MODE == 3) {
                    const float* rr = ga.res + (size_t)row*Nloc + col;
                    o0 += rr[0]; o1 += rr[1];
                } else if (MODE == 4) {
                    const float* rr = ga.res + (size_t)row*Nloc + col;
                    float g0 = rr[0], g1 = rr[1];
                    o0 *= g0 / (1.0f + __expf(-g0));
                    o1 *= g1 / (1.0f + __expf(-g1));
                }
                float2 ov = make_float2(o0, o1);
                *(float2*)&Cp[(size_t)row*Nloc + col] = ov;
            }
        }
    }
}

// ---------------- RoPE (in-place on q and k buffers) ----------------
__global__ __launch_bounds__(256) void rope_kernel(float* __restrict__ q,
                                                   float* __restrict__ k)
{
    int idx = blockIdx.x * blockDim.x + threadIdx.x;
    if (idx >= MROWS * 16 * 32) return;
    int i   = idx & 31;
    int hs  = (idx >> 5) & 15;
    int tok = idx >> 9;
    int pos = tok & 2047;
    float invf = powf(1.0e6f, -(float)i * (1.0f/32.0f));
    float fr = (float)pos * invf;
    float sn, cs; sincosf(fr, &sn, &cs);
    float* base;
    if (hs < NHC) base = q + (size_t)tok*HIDC + hs*HDC;
    else          base = k + (size_t)tok*(NKVC*HDC) + (hs - NHC)*HDC;
    float v1 = base[i], v2 = base[i+32];
    base[i]    = v1*cs - v2*sn;
    base[i+32] = v2*cs + v1*sn;
}

// ---------------- Attention (flash, 64q x 64k tiles, fp32 SIMT) ----------------
__global__ __launch_bounds__(256) void attn_kernel(
    const float* __restrict__ q, const float* __restrict__ k,
    const float* __restrict__ v, float* __restrict__ o)
{
    extern __shared__ float sm[];
    float* qs = sm;                 // [64][68]
    float* ks = sm + 64*68;
    float* vs = sm + 2*64*68;
    int qb = blockIdx.x, h = blockIdx.y, b = blockIdx.z;
    int tid = threadIdx.x, lane = tid & 31;
    int r = tid >> 2, j = tid & 3, j16 = j << 4;
    int kvh = h / 7;

    const float* qbase = q + (size_t)(b*SS + qb*64) * HIDC + h*HDC;
    for (int idx = tid; idx < 4096; idx += 256) {
        int row = idx >> 6, d = idx & 63;
        qs[row*68 + d] = qbase[(size_t)row*HIDC + d] * 0.125f;
    }
    const float* kb0 = k + (size_t)b*SS*(NKVC*HDC) + kvh*HDC;
    const float* vb0 = v + (size_t)b*SS*(NKVC*HDC) + kvh*HDC;

    float4 acc4[4];
#pragma unroll
    for (int t = 0; t < 4; t++) acc4[t] = make_float4(0.f,0.f,0.f,0.f);
    float mrow = -INFINITY, lrow = 0.f;
    int sqr = qb*64 + r;
    int ntiles = (qb + 1 > 24) ? (qb + 1) : 24;

    for (int t = 0; t < ntiles; t++) {
        __syncthreads();
        int kbase = t * 64;
        for (int idx = tid; idx < 4096; idx += 256) {
            int row = idx >> 6, d = idx & 63;
            ks[row*68 + d] = kb0[(size_t)(kbase+row)*(NKVC*HDC) + d];
            vs[row*68 + d] = vb0[(size_t)(kbase+row)*(NKVC*HDC) + d];
        }
        __syncthreads();

        float e[16];
#pragma unroll
        for (int i = 0; i < 16; i++) e[i] = 0.f;
        const float* qrow = &qs[r*68];
#pragma unroll
        for (int dc = 0; dc < 4; dc++) {
            float4 q4[4];
#pragma unroll
            for (int tt = 0; tt < 4; tt++) q4[tt] = *(const float4*)(qrow + dc*16 + tt*4);
#pragma unroll
            for (int i = 0; i < 16; i++) {
                const float* kr = &ks[(4*i + j)*68 + dc*16];
#pragma unroll
                for (int tt = 0; tt < 4; tt++) {
                    float4 k4 = *(const float4*)(kr + tt*4);
                    e[i] = fmaf(q4[tt].x, k4.x,
                           fmaf(q4[tt].y, k4.y,
                           fmaf(q4[tt].z, k4.z,
                           fmaf(q4[tt].w, k4.w, e[i]))));
                }
            }
        }
        bool full = (kbase + 63 < S0C) || (kbase + 63 <= sqr);
        float tmax = -INFINITY;
        if (full) {
#pragma unroll
            for (int i = 0; i < 16; i++) tmax = fmaxf(tmax, e[i]);
        } else {
#pragma unroll
            for (int i = 0; i < 16; i++) {
                int kk = kbase + 4*i + j;
                if (!(kk < S0C || kk <= sqr)) e[i] = -INFINITY;
                tmax = fmaxf(tmax, e[i]);
            }
        }
        tmax = fmaxf(tmax, __shfl_xor_sync(0xffffffffu, tmax, 1));
        tmax = fmaxf(tmax, __shfl_xor_sync(0xffffffffu, tmax, 2));
        float mnew = fmaxf(mrow, tmax);
        float corr = __expf(mrow - mnew);
        lrow *= corr;
#pragma unroll
        for (int t4 = 0; t4 < 4; t4++) {
            acc4[t4].x *= corr; acc4[t4].y *= corr;
            acc4[t4].z *= corr; acc4[t4].w *= corr;
        }
        float rsum = 0.f;
#pragma unroll
        for (int i = 0; i < 16; i++) { e[i] = __expf(e[i] - mnew); rsum += e[i]; }
        rsum += __shfl_xor_sync(0xffffffffu, rsum, 1);
        rsum += __shfl_xor_sync(0xffffffffu, rsum, 2);
        lrow += rsum;
        mrow = mnew;

#pragma unroll
        for (int c = 0; c < 64; c++) {
            float p = __shfl_sync(0xffffffffu, e[c >> 2], (lane & ~3) | (c & 3));
            const float* vr = &vs[c*68 + j16];
#pragma unroll
            for (int t4 = 0; t4 < 4; t4++) {
                float4 v4 = *(const float4*)(vr + t4*4);
                acc4[t4].x = fmaf(p, v4.x, acc4[t4].x);
                acc4[t4].y = fmaf(p, v4.y, acc4[t4].y);
                acc4[t4].z = fmaf(p, v4.z, acc4[t4].z);
                acc4[t4].w = fmaf(p, v4.w, acc4[t4].w);
            }
        }
    }

    float inv = 1.0f / lrow;
    float* op = o + (size_t)(b*SS + sqr) * HIDC + h*HDC + j16;
#pragma unroll
    for (int t4 = 0; t4 < 4; t4++) {
        float4 ov = acc4[t4];
        ov.x *= inv; ov.y *= inv; ov.z *= inv; ov.w *= inv;
        *(float4*)(op + t4*4) = ov;
    }
}

// ---------------- launcher ----------------
extern "C" void kernel_launch(void* const* d_in, const int* in_sizes, int n_in,
                              void* d_out, int out_size)
{
    const float* x0  = (const float*)d_in[0];
    const float* x1  = (const float*)d_in[1];
    const float* x2  = (const float*)d_in[2];
    const float* qW  = (const float*)d_in[3];
    const float* qb  = (const float*)d_in[4];
    const float* kW  = (const float*)d_in[5];
    const float* kb  = (const float*)d_in[6];
    const float* vW  = (const float*)d_in[7];
    const float* vb  = (const float*)d_in[8];
    const float* oW  = (const float*)d_in[9];
    const float* ln1 = (const float*)d_in[10];
    const float* ln2 = (const float*)d_in[11];
    const float* gW  = (const float*)d_in[12];
    const float* uW  = (const float*)d_in[13];
    const float* dW  = (const float*)d_in[14];
    float* out = (float*)d_out;

    float* sb = nullptr;
    cudaGetSymbolAddress((void**)&sb, g_buf);
    float* hb   = sb + OFF_H;
    float* qbuf = sb + OFF_Q;
    float* kbuf = sb + OFF_K;
    float* vbuf = sb + OFF_V;
    float* att  = sb + OFF_ATT;
    float* o1   = sb + OFF_O1;
    float* h2   = sb + OFF_H2;
    float* gb   = sb + OFF_G;

    // 1. pre-attention RMSNorm
    rms_kernel<0><<<512, 256>>>(x0, x1, x2, nullptr, ln1, hb);

    // 2. fused QKV (+bias) on tensor cores
    {
        GArgs ga = {};
        ga.A = hb; ga.W = qW; ga.bias = qb; ga.C = qbuf;
        ga.W2 = kW; ga.b2 = kb; ga.C2 = kbuf;
        ga.W3 = vW; ga.b3 = vb; ga.C3 = vbuf;
        ga.K = HIDC;
        gemm_tc<5><<<dim3(9, 32), 256>>>(ga);
    }
    // 3. RoPE
    rope_kernel<<<8192, 256>>>(qbuf, kbuf);
    // 4. attention
    cudaFuncSetAttribute(attn_kernel, cudaFuncAttributeMaxDynamicSharedMemorySize, 53248);
    attn_kernel<<<dim3(32, NHC, BB), 256, 3*64*68*4>>>(qbuf, kbuf, vbuf, att);
    // 5. o-proj + residual(x)
    {
        GArgs ga = {};
        ga.A = att; ga.W = oW; ga.C = o1; ga.N = HIDC; ga.K = HIDC;
        ga.x0 = x0; ga.x1 = x1; ga.x2 = x2;
        gemm_tc<2><<<dim3(7, 32), 256>>>(ga);
    }
    // 6. post-attention RMSNorm
    rms_kernel<1><<<512, 256>>>(nullptr, nullptr, nullptr, o1, ln2, h2);
    // 7. gate proj
    {
        GArgs ga = {};
        ga.A = h2; ga.W = gW; ga.C = gb; ga.N = INTERC; ga.K = HIDC;
        gemm_tc<1><<<dim3(38, 32), 256>>>(ga);
    }
    // 8. up proj fused with silu(g)*u (in-place on gb)
    {
        GArgs ga = {};
        ga.A = h2; ga.W = uW; ga.res = gb; ga.C = gb; ga.N = INTERC; ga.K = HIDC;
        gemm_tc<4><<<dim3(38, 32), 256>>>(ga);
    }
    // 9. down-proj + residual(o1) -> output
    {
        GArgs ga = {};
        ga.A = gb; ga.W = dW; ga.res = o1; ga.C = out; ga.N = HIDC; ga.K = INTERC;
        gemm_tc<3><<<dim3(7, 32), 256>>>(ga);
    }
}

// round 5
// speedup vs baseline: 3.4716x; 2.1357x over previous
#include <cuda_runtime.h>
#include <math.h>

// ---------------- problem constants ----------------
#define BB     2
#define S0C    1536
#define S1C    384
#define S2C    128
#define SS     2048
#define HIDC   896
#define NHC    14
#define NKVC   2
#define HDC    64
#define INTERC 4864
#define MROWS  (BB*SS)          // 4096 token rows

// ---------------- scratch (device global, allocation-free) ----------------
#define OFF_H   0ull
#define OFF_Q   3670016ull
#define OFF_K   7340032ull
#define OFF_V   7864320ull
#define OFF_ATT 8388608ull
#define OFF_O1  12058624ull
#define OFF_H2  15728640ull
#define OFF_G   19398656ull
#define SCRATCH_FLOATS 39321600ull

__device__ float g_buf[SCRATCH_FLOATS];

// ---------------- RMSNorm (warp per token) ----------------
template<int SRC>
__global__ __launch_bounds__(256) void rms_kernel(
    const float* __restrict__ x0, const float* __restrict__ x1,
    const float* __restrict__ x2, const float* __restrict__ inbuf,
    const float* __restrict__ w, float* __restrict__ out)
{
    int warp = (blockIdx.x * blockDim.x + threadIdx.x) >> 5;
    if (warp >= MROWS) return;
    int lane = threadIdx.x & 31;
    int b = warp >> 11, s = warp & 2047;
    const float* xp;
    int seg;
    if (SRC == 0) {
        if (s < S0C)            { seg = 0; xp = x0 + ((size_t)b*S0C + s)        * HIDC; }
        else if (s < S0C+S1C)   { seg = 1; xp = x1 + ((size_t)b*S1C + (s-S0C))  * HIDC; }
        else                    { seg = 2; xp = x2 + ((size_t)b*S2C + (s-S0C-S1C)) * HIDC; }
    } else {
        seg = (s < S0C) ? 0 : ((s < S0C+S1C) ? 1 : 2);
        xp = inbuf + (size_t)warp * HIDC;
    }
    float vals[28];
    float ss = 0.f;
#pragma unroll
    for (int i = 0; i < 28; i++) { float v = xp[lane + i*32]; vals[i] = v; ss += v*v; }
#pragma unroll
    for (int o = 16; o > 0; o >>= 1) ss += __shfl_xor_sync(0xffffffffu, ss, o);
    float rs = rsqrtf(ss * (1.0f/896.0f) + 1e-6f);
    const float* wp = w + seg * HIDC;
    float* op = out + (size_t)warp * HIDC;
#pragma unroll
    for (int i = 0; i < 28; i++) { int c = lane + i*32; op[c] = vals[i] * rs * wp[c]; }
}

// ---------------- TF32 helpers ----------------
__device__ __forceinline__ unsigned f2t(float f) {
    unsigned u; asm("cvt.rna.tf32.f32 %0, %1;" : "=r"(u) : "f"(f)); return u;
}

__device__ __forceinline__ void mma8(float* c, const unsigned* a, const unsigned* b) {
    asm volatile(
        "mma.sync.aligned.m16n8k8.row.col.f32.tf32.tf32.f32 "
        "{%0,%1,%2,%3}, {%4,%5,%6,%7}, {%8,%9}, {%0,%1,%2,%3};"
        : "+f"(c[0]), "+f"(c[1]), "+f"(c[2]), "+f"(c[3])
        : "r"(a[0]), "r"(a[1]), "r"(a[2]), "r"(a[3]), "r"(b[0]), "r"(b[1]));
}

// ---------------- TF32 tensor-core GEMM ----------------
// C[M,N] = A[M,K] @ W[seg,N,K]^T (+ epilogue)
// BM=128, BN=128, BK=16, 256 threads, warps 2(m) x 4(n), warp tile 64x32.
// MODE 1: plain (gate)     MODE 2: += x residual (o-proj)
// MODE 3: += res (down)    MODE 4: C = silu(res)*acc (up+SwiGLU)
// MODE 5: fused QKV (+bias), blockIdx.x: 0-6 q, 7 k, 8 v

struct GArgs {
    const float* A; const float* W; const float* bias; const float* res;
    float* C; int N; int K;
    const float* x0; const float* x1; const float* x2;
    const float* W2; const float* W3; const float* b2; const float* b3;
    float* C2; float* C3;
};

// store one float4 (k4*4..+3) of row m, with k-skew swizzle
__device__ __forceinline__ void stile(unsigned (*S)[136], int k4, int m, float4 v) {
    int mp = (m + 8*k4) & 127;
    S[k4*4+0][mp] = f2t(v.x);
    S[k4*4+1][mp] = f2t(v.y);
    S[k4*4+2][mp] = f2t(v.z);
    S[k4*4+3][mp] = f2t(v.w);
}

template<int MODE>
__global__ __launch_bounds__(256, 2) void gemm_tc(GArgs ga)
{
    __shared__ unsigned As[2][16][136];
    __shared__ unsigned Bs[2][16][136];
    int tid = threadIdx.x;
    int mb = blockIdx.y * 128;
    int srow = mb & 2047;
    int seg = (srow < S0C) ? 0 : ((srow < S0C+S1C) ? 1 : 2);

    const float* Wp; const float* bp = nullptr; float* Cp; int Nloc; int nb;
    if (MODE == 5) {
        int bx = blockIdx.x;
        if (bx < 7)       { Wp = ga.W;  bp = ga.bias; Cp = ga.C;  Nloc = 896; nb = bx*128; }
        else if (bx == 7) { Wp = ga.W2; bp = ga.b2;   Cp = ga.C2; Nloc = 128; nb = 0; }
        else              { Wp = ga.W3; bp = ga.b3;   Cp = ga.C3; Nloc = 128; nb = 0; }
        bp += seg * Nloc;
    } else {
        Wp = ga.W; Cp = ga.C; Nloc = ga.N; nb = blockIdx.x * 128;
    }
    int K = ga.K;
    Wp += (size_t)seg * Nloc * K;

    int ldr  = tid >> 2;
    int ldk4 = tid & 3;
    const float* Ap = ga.A + (size_t)(mb + ldr) * K + ldk4*4;
    const float* Bp = Wp   + (size_t)(nb + ldr) * K + ldk4*4;
    size_t rowsk = (size_t)64 * K;

    int lane = tid & 31;
    int g = lane >> 2, tq = lane & 3;
    int w = tid >> 5;
    int warp_m = (w & 1) * 64, warp_n = (w >> 1) * 32;

    float acc[4][4][4];
#pragma unroll
    for (int i = 0; i < 4; i++)
#pragma unroll
        for (int jn = 0; jn < 4; jn++)
#pragma unroll
            for (int cc = 0; cc < 4; cc++) acc[i][jn][cc] = 0.f;

    int nsteps = K >> 4;

    {
        float4 a0 = *(const float4*)Ap;
        float4 a1 = *(const float4*)(Ap + rowsk);
        float4 b0 = *(const float4*)Bp;
        float4 b1 = *(const float4*)(Bp + rowsk);
        stile(As[0], ldk4, ldr,     a0);
        stile(As[0], ldk4, ldr+64,  a1);
        stile(Bs[0], ldk4, ldr,     b0);
        stile(Bs[0], ldk4, ldr+64,  b1);
        Ap += 16; Bp += 16;
    }

    for (int s = 0; s < nsteps; s++) {
        __syncthreads();
        int cur = s & 1;
        float4 na0, na1, nb0, nb1;
        bool more = (s + 1 < nsteps);
        if (more) {
            na0 = *(const float4*)Ap;
            na1 = *(const float4*)(Ap + rowsk);
            nb0 = *(const float4*)Bp;
            nb1 = *(const float4*)(Bp + rowsk);
            Ap += 16; Bp += 16;
        }
#pragma unroll
        for (int ks = 0; ks < 2; ks++) {
            int kb = ks * 8;
            int off0 = (kb >> 2) * 8;
            int off1 = off0 + 8;
            unsigned af[4][4];
#pragma unroll
            for (int mt = 0; mt < 4; mt++) {
                int mA = warp_m + mt*16 + g;
                af[mt][0] = As[cur][kb+tq  ][(mA      + off0) & 127];
                af[mt][1] = As[cur][kb+tq  ][(mA + 8  + off0) & 127];
                af[mt][2] = As[cur][kb+tq+4][(mA      + off1) & 127];
                af[mt][3] = As[cur][kb+tq+4][(mA + 8  + off1) & 127];
            }
            unsigned bf[4][2];
#pragma unroll
            for (int nt = 0; nt < 4; nt++) {
                int nB = warp_n + nt*8 + g;
                bf[nt][0] = Bs[cur][kb+tq  ][(nB + off0) & 127];
                bf[nt][1] = Bs[cur][kb+tq+4][(nB + off1) & 127];
            }
#pragma unroll
            for (int mt = 0; mt < 4; mt++)
#pragma unroll
                for (int nt = 0; nt < 4; nt++)
                    mma8(acc[mt][nt], af[mt], bf[nt]);
        }
        if (more) {
            int nxt = cur ^ 1;
            stile(As[nxt], ldk4, ldr,    na0);
            stile(As[nxt], ldk4, ldr+64, na1);
            stile(Bs[nxt], ldk4, ldr,    nb0);
            stile(Bs[nxt], ldk4, ldr+64, nb1);
        }
    }

    const float* xp = nullptr; int xstart = 0, xseq = 0;
    if (MODE == 2) {
        if (seg == 0)      { xp = ga.x0; xstart = 0;       xseq = S0C; }
        else if (seg == 1) { xp = ga.x1; xstart = S0C;     xseq = S1C; }
        else               { xp = ga.x2; xstart = S0C+S1C; xseq = S2C; }
    }

#pragma unroll
    for (int mt = 0; mt < 4; mt++) {
#pragma unroll
        for (int hh = 0; hh < 2; hh++) {
            int row = mb + warp_m + mt*16 + g + hh*8;
#pragma unroll
            for (int nt = 0; nt < 4; nt++) {
                int col = nb + warp_n + nt*8 + 2*tq;
                float o0 = acc[mt][nt][hh*2 + 0];
                float o1 = acc[mt][nt][hh*2 + 1];
                if (MODE == 5) {
                    o0 += bp[col]; o1 += bp[col+1];
                } else if (MODE == 2) {
                    int b = row >> 11, s = row & 2047;
                    const float* rr = xp + ((size_t)b*xseq + (s - xstart))*HIDC + col;
                    o0 += rr[0]; o1 += rr[1];
                } else if (MODE == 3) {
                    const float* rr = ga.res + (size_t)row*Nloc + col;
                    o0 += rr[0]; o1 += rr[1];
                } else if (MODE == 4) {
                    const float* rr = ga.res + (size_t)row*Nloc + col;
                    float g0 = rr[0], g1 = rr[1];
                    o0 *= g0 / (1.0f + __expf(-g0));
                    o1 *= g1 / (1.0f + __expf(-g1));
                }
                float2 ov = make_float2(o0, o1);
                *(float2*)&Cp[(size_t)row*Nloc + col] = ov;
            }
        }
    }
}

// ---------------- RoPE (in-place on q and k buffers) ----------------
__global__ __launch_bounds__(256) void rope_kernel(float* __restrict__ q,
                                                   float* __restrict__ k)
{
    int idx = blockIdx.x * blockDim.x + threadIdx.x;
    if (idx >= MROWS * 16 * 32) return;
    int i   = idx & 31;
    int hs  = (idx >> 5) & 15;
    int tok = idx >> 9;
    int pos = tok & 2047;
    // 1/theta^(i/32) = exp2(-i/32 * log2(1e6))
    float invf = exp2f(-(float)i * (19.931568569324174f/32.0f));
    float fr = (float)pos * invf;
    float sn, cs; sincosf(fr, &sn, &cs);
    float* base;
    if (hs < NHC) base = q + (size_t)tok*HIDC + hs*HDC;
    else          base = k + (size_t)tok*(NKVC*HDC) + (hs - NHC)*HDC;
    float v1 = base[i], v2 = base[i+32];
    base[i]    = v1*cs - v2*sn;
    base[i+32] = v2*cs + v1*sn;
}

// ---------------- Tensor-core flash attention ----------------
// 128 q rows per block, 64-key tiles, 8 warps, 256 threads.
// Warp w owns q-rows [w*16, w*16+16): one m16 slab across all 64 key cols / 64 d.
// K tile stored d-major transposed ks[d][72]; V tile vs[kcol][72]; P in ps[row][68].
// All operands tf32; accumulation fp32; softmax fp32 in registers.
#define AT_KS_OFF  0          // ks: [64][72] unsigned
#define AT_VS_OFF  (64*72)    // vs: [64][72] unsigned
#define AT_PS_OFF  (2*64*72)  // ps: [128][68] unsigned
#define AT_SMEM_BYTES ((2*64*72 + 128*68) * 4)

__global__ __launch_bounds__(256, 1) void attn_tc(
    const float* __restrict__ q, const float* __restrict__ k,
    const float* __restrict__ v, float* __restrict__ o)
{
    extern __shared__ unsigned smu[];
    unsigned (*ks)[72] = (unsigned(*)[72])(smu + AT_KS_OFF);
    unsigned (*vs)[72] = (unsigned(*)[72])(smu + AT_VS_OFF);
    unsigned (*ps)[68] = (unsigned(*)[68])(smu + AT_PS_OFF);

    int qb = blockIdx.x, h = blockIdx.y, b = blockIdx.z;
    int tid = threadIdx.x, lane = tid & 31, w = tid >> 5;
    int g = lane >> 2, tq = lane & 3;
    int kvh = h / 7;

    // Q fragments: rows w*16+g, +8; all 64 d; scaled by 1/8, tf32
    unsigned qf[8][4];
    {
        const float* qp = q + ((size_t)(b*SS + qb*128 + w*16)) * HIDC + h*HDC;
        const float* q0 = qp + (size_t)g * HIDC;
        const float* q1 = qp + (size_t)(g+8) * HIDC;
#pragma unroll
        for (int kk = 0; kk < 8; kk++) {
            qf[kk][0] = f2t(q0[kk*8 + tq]     * 0.125f);
            qf[kk][1] = f2t(q1[kk*8 + tq]     * 0.125f);
            qf[kk][2] = f2t(q0[kk*8 + tq + 4] * 0.125f);
            qf[kk][3] = f2t(q1[kk*8 + tq + 4] * 0.125f);
        }
    }

    float oacc[8][4];
#pragma unroll
    for (int nt = 0; nt < 8; nt++)
#pragma unroll
        for (int cc = 0; cc < 4; cc++) oacc[nt][cc] = 0.f;

    float mrow0 = -INFINITY, mrow1 = -INFINITY;
    float lrow0 = 0.f, lrow1 = 0.f;
    int r0 = qb*128 + w*16 + g;     // rows for c0,c1; r0+8 for c2,c3
    int r1 = r0 + 8;
    int pr0 = w*16 + g, pr1 = pr0 + 8;

    const float* kb0 = k + (size_t)b*SS*(NKVC*HDC) + kvh*HDC;
    const float* vb0 = v + (size_t)b*SS*(NKVC*HDC) + kvh*HDC;

    int nt24 = 2*qb + 2;
    int ntiles = nt24 > 24 ? nt24 : 24;    // prefix = 24 tiles always visible

    int fkcol = tid & 63;
    int fdbase = (tid >> 6) << 4;

    for (int t = 0; t < ntiles; t++) {
        int kbase = t * 64;
        __syncthreads();
        // fill ks (transposed, tf32) and vs (row-major, tf32)
        {
            const float* krow = kb0 + (size_t)(kbase + fkcol)*(NKVC*HDC) + fdbase;
            const float* vrow = vb0 + (size_t)(kbase + fkcol)*(NKVC*HDC) + fdbase;
#pragma unroll
            for (int i = 0; i < 4; i++) {
                float4 kx = *(const float4*)(krow + i*4);
                ks[fdbase + i*4 + 0][fkcol] = f2t(kx.x);
                ks[fdbase + i*4 + 1][fkcol] = f2t(kx.y);
                ks[fdbase + i*4 + 2][fkcol] = f2t(kx.z);
                ks[fdbase + i*4 + 3][fkcol] = f2t(kx.w);
                float4 vx = *(const float4*)(vrow + i*4);
                uint4 vv;
                vv.x = f2t(vx.x); vv.y = f2t(vx.y); vv.z = f2t(vx.z); vv.w = f2t(vx.w);
                *(uint4*)&vs[fkcol][fdbase + i*4] = vv;
            }
        }
        __syncthreads();

        // S = Q @ K^T  (8 n-tiles of 8 key cols)
        float sacc[8][4];
#pragma unroll
        for (int nt = 0; nt < 8; nt++)
#pragma unroll
            for (int cc = 0; cc < 4; cc++) sacc[nt][cc] = 0.f;
#pragma unroll
        for (int kk = 0; kk < 8; kk++) {
            int b0r = kk*8 + tq, b1r = b0r + 4;
#pragma unroll
            for (int nt = 0; nt < 8; nt++) {
                unsigned bb[2] = { ks[b0r][nt*8 + g], ks[b1r][nt*8 + g] };
                mma8(sacc[nt], qf[kk], bb);
            }
        }

        // mask
        bool full = (kbase + 63 < S0C) || (kbase + 63 <= r0);
        if (!full) {
#pragma unroll
            for (int nt = 0; nt < 8; nt++) {
                int c0 = kbase + nt*8 + 2*tq;
                int c1 = c0 + 1;
                if (!(c0 < S0C || c0 <= r0)) sacc[nt][0] = -INFINITY;
                if (!(c1 < S0C || c1 <= r0)) sacc[nt][1] = -INFINITY;
                if (!(c0 < S0C || c0 <= r1)) sacc[nt][2] = -INFINITY;
                if (!(c1 < S0C || c1 <= r1)) sacc[nt][3] = -INFINITY;
            }
        }

        // row max (quad reduce)
        float mx0 = -INFINITY, mx1 = -INFINITY;
#pragma unroll
        for (int nt = 0; nt < 8; nt++) {
            mx0 = fmaxf(mx0, fmaxf(sacc[nt][0], sacc[nt][1]));
            mx1 = fmaxf(mx1, fmaxf(sacc[nt][2], sacc[nt][3]));
        }
        mx0 = fmaxf(mx0, __shfl_xor_sync(0xffffffffu, mx0, 1));
        mx0 = fmaxf(mx0, __shfl_xor_sync(0xffffffffu, mx0, 2));
        mx1 = fmaxf(mx1, __shfl_xor_sync(0xffffffffu, mx1, 1));
        mx1 = fmaxf(mx1, __shfl_xor_sync(0xffffffffu, mx1, 2));
        float m0 = fmaxf(mrow0, mx0);
        float m1 = fmaxf(mrow1, mx1);
        float cr0 = __expf(mrow0 - m0);
        float cr1 = __expf(mrow1 - m1);

        // exp, P -> smem (tf32), row sums
        float s0 = 0.f, s1 = 0.f;
#pragma unroll
        for (int nt = 0; nt < 8; nt++) {
            float p0 = __expf(sacc[nt][0] - m0);
            float p1 = __expf(sacc[nt][1] - m0);
            float p2 = __expf(sacc[nt][2] - m1);
            float p3 = __expf(sacc[nt][3] - m1);
            s0 += p0 + p1; s1 += p2 + p3;
            uint2 u0; u0.x = f2t(p0); u0.y = f2t(p1);
            uint2 u1; u1.x = f2t(p2); u1.y = f2t(p3);
            *(uint2*)&ps[pr0][nt*8 + 2*tq] = u0;
            *(uint2*)&ps[pr1][nt*8 + 2*tq] = u1;
        }
        s0 += __shfl_xor_sync(0xffffffffu, s0, 1);
        s0 += __shfl_xor_sync(0xffffffffu, s0, 2);
        s1 += __shfl_xor_sync(0xffffffffu, s1, 1);
        s1 += __shfl_xor_sync(0xffffffffu, s1, 2);
        lrow0 = lrow0 * cr0 + s0;
        lrow1 = lrow1 * cr1 + s1;
        mrow0 = m0; mrow1 = m1;

        // rescale O
#pragma unroll
        for (int nt = 0; nt < 8; nt++) {
            oacc[nt][0] *= cr0; oacc[nt][1] *= cr0;
            oacc[nt][2] *= cr1; oacc[nt][3] *= cr1;
        }

        __syncwarp();   // P writes visible to whole warp

        // O += P @ V  (A = own P rows from smem, B = V)
#pragma unroll
        for (int kk = 0; kk < 8; kk++) {
            unsigned af[4];
            af[0] = ps[pr0][kk*8 + tq];
            af[1] = ps[pr1][kk*8 + tq];
            af[2] = ps[pr0][kk*8 + tq + 4];
            af[3] = ps[pr1][kk*8 + tq + 4];
            int b0r = kk*8 + tq, b1r = b0r + 4;
#pragma unroll
            for (int nt = 0; nt < 8; nt++) {
                unsigned bb[2] = { vs[b0r][nt*8 + g], vs[b1r][nt*8 + g] };
                mma8(oacc[nt], af, bb);
            }
        }
        __syncwarp();   // P reads done before next tile overwrites
    }

    // normalize + store
    float i0 = 1.f / lrow0, i1 = 1.f / lrow1;
    float* op0 = o + (size_t)(b*SS + r0) * HIDC + h*HDC;
    float* op1 = op0 + (size_t)8 * HIDC;
#pragma unroll
    for (int nt = 0; nt < 8; nt++) {
        int col = nt*8 + 2*tq;
        float2 v0 = make_float2(oacc[nt][0]*i0, oacc[nt][1]*i0);
        float2 v1 = make_float2(oacc[nt][2]*i1, oacc[nt][3]*i1);
        *(float2*)&op0[col] = v0;
        *(float2*)&op1[col] = v1;
    }
}

// ---------------- launcher ----------------
extern "C" void kernel_launch(void* const* d_in, const int* in_sizes, int n_in,
                              void* d_out, int out_size)
{
    const float* x0  = (const float*)d_in[0];
    const float* x1  = (const float*)d_in[1];
    const float* x2  = (const float*)d_in[2];
    const float* qW  = (const float*)d_in[3];
    const float* qb  = (const float*)d_in[4];
    const float* kW  = (const float*)d_in[5];
    const float* kb  = (const float*)d_in[6];
    const float* vW  = (const float*)d_in[7];
    const float* vb  = (const float*)d_in[8];
    const float* oW  = (const float*)d_in[9];
    const float* ln1 = (const float*)d_in[10];
    const float* ln2 = (const float*)d_in[11];
    const float* gW  = (const float*)d_in[12];
    const float* uW  = (const float*)d_in[13];
    const float* dW  = (const float*)d_in[14];
    float* out = (float*)d_out;

    float* sb = nullptr;
    cudaGetSymbolAddress((void**)&sb, g_buf);
    float* hb   = sb + OFF_H;
    float* qbuf = sb + OFF_Q;
    float* kbuf = sb + OFF_K;
    float* vbuf = sb + OFF_V;
    float* att  = sb + OFF_ATT;
    float* o1   = sb + OFF_O1;
    float* h2   = sb + OFF_H2;
    float* gb   = sb + OFF_G;

    // 1. pre-attention RMSNorm
    rms_kernel<0><<<512, 256>>>(x0, x1, x2, nullptr, ln1, hb);

    // 2. fused QKV (+bias) on tensor cores
    {
        GArgs ga = {};
        ga.A = hb; ga.W = qW; ga.bias = qb; ga.C = qbuf;
        ga.W2 = kW; ga.b2 = kb; ga.C2 = kbuf;
        ga.W3 = vW; ga.b3 = vb; ga.C3 = vbuf;
        ga.K = HIDC;
        gemm_tc<5><<<dim3(9, 32), 256>>>(ga);
    }
    // 3. RoPE
    rope_kernel<<<8192, 256>>>(qbuf, kbuf);
    // 4. attention (tensor core)
    cudaFuncSetAttribute(attn_tc, cudaFuncAttributeMaxDynamicSharedMemorySize, AT_SMEM_BYTES);
    attn_tc<<<dim3(16, NHC, BB), 256, AT_SMEM_BYTES>>>(qbuf, kbuf, vbuf, att);
    // 5. o-proj + residual(x)
    {
        GArgs ga = {};
        ga.A = att; ga.W = oW; ga.C = o1; ga.N = HIDC; ga.K = HIDC;
        ga.x0 = x0; ga.x1 = x1; ga.x2 = x2;
        gemm_tc<2><<<dim3(7, 32), 256>>>(ga);
    }
    // 6. post-attention RMSNorm
    rms_kernel<1><<<512, 256>>>(nullptr, nullptr, nullptr, o1, ln2, h2);
    // 7. gate proj
    {
        GArgs ga = {};
        ga.A = h2; ga.W = gW; ga.C = gb; ga.N = INTERC; ga.K = HIDC;
        gemm_tc<1><<<dim3(38, 32), 256>>>(ga);
    }
    // 8. up proj fused with silu(g)*u (in-place on gb)
    {
        GArgs ga = {};
        ga.A = h2; ga.W = uW; ga.res = gb; ga.C = gb; ga.N = INTERC; ga.K = HIDC;
        gemm_tc<4><<<dim3(38, 32), 256>>>(ga);
    }
    // 9. down-proj + residual(o1) -> output
    {
        GArgs ga = {};
        ga.A = gb; ga.W = dW; ga.res = o1; ga.C = out; ga.N = HIDC; ga.K = INTERC;
        gemm_tc<3><<<dim3(7, 32), 256>>>(ga);
    }
}